// round 17
// baseline (speedup 1.0000x reference)
#include <cuda_runtime.h>
#include <cstdint>

#define Bb 256
#define Tt 1024
#define Vv 128
#define Hh 128
#define NSM 152          // GB300 sm_103a active SMs
#define NSOLO (Bb - NSM) // 104 paired bids -> 48 solo bids (104..151)

// Scratch (no allocations allowed).
__device__ unsigned char g_symbols[Bb * Tt];
__device__ float g_Wtbl[128 * Hh];   // row s = W_ih[:, s-1]; row 0 = zeros
__device__ int g_len[Bb];
__device__ int g_assign[Bb];   // bid -> batch element

// ---------------------------------------------------------------------------
// Kernel 0: lengths (blocks 0..255) + W_ih table build (blocks 256..383).
// x[b,t,0] == 1.0 iff symbol==0 (pad). length = first pad.
// ---------------------------------------------------------------------------
__global__ void prep_kernel(const float* __restrict__ x,
                            const float* __restrict__ W_ih) {
    if (blockIdx.x >= Bb) {
        int s = blockIdx.x - Bb;   // 0..127 (table row)
        int h = threadIdx.x;       // 0..127
        g_Wtbl[s * Hh + h] = (s == 0) ? 0.0f : W_ih[h * 127 + (s - 1)];
        return;
    }
    __shared__ int smin;
    const int b = blockIdx.x;
    if (threadIdx.x == 0) smin = Tt;
    __syncthreads();
    int local = Tt;
    for (int t = threadIdx.x; t < Tt; t += 128) {
        float v = __ldcs(x + ((size_t)b * Tt + t) * Vv);
        if (v > 0.5f && t < local) local = t;
    }
#pragma unroll
    for (int o = 16; o; o >>= 1) {
        int other = __shfl_xor_sync(0xffffffffu, local, o);
        local = min(local, other);
    }
    if ((threadIdx.x & 31) == 0) atomicMin(&smin, local);
    __syncthreads();
    if (threadIdx.x == 0) g_len[b] = smin;
}

// ---------------------------------------------------------------------------
// Kernel 0b: length-aware CTA->SM schedule (proven in R7).
// Classic placement: bids b and b+NSM co-resident; bids 104..151 solo.
// Solo slots get the longest sequences; the rest pair anti-sorted.
// ---------------------------------------------------------------------------
__global__ void schedule_kernel() {
    __shared__ int slen[Bb];
    int b = threadIdx.x;           // 256 threads
    slen[b] = g_len[b];
    __syncthreads();
    int Lb = slen[b];
    int rank = 0;
#pragma unroll 8
    for (int j = 0; j < Bb; j++) {
        int Lj = slen[j];
        rank += (Lj > Lb) || (Lj == Lb && j < b);
    }
    int slot;
    if (rank < NSOLO)            slot = (NSM - NSOLO) + rank;   // 104..151 solo
    else if (rank < NSM)         slot = rank - NSOLO;           // 0..103
    else                         slot = (Bb - 1 - rank) + NSM;  // 152..255
    g_assign[slot] = b;
}

// ---------------------------------------------------------------------------
// Kernel 1: extract symbol index from one-hot rows. Warp per (b,t) row.
// ---------------------------------------------------------------------------
__global__ void sym_kernel(const float* __restrict__ x) {
    int row  = blockIdx.x * 8 + (threadIdx.x >> 5);
    int lane = threadIdx.x & 31;
    int b = row >> 10;        // row / Tt
    int t = row & (Tt - 1);
    if (t >= g_len[b]) {
        if (lane == 0) g_symbols[row] = 0;
        return;
    }
    float4 v = __ldcs(reinterpret_cast<const float4*>(x + (size_t)row * Vv) + lane);
    int idx = 0;
    if (v.x > 0.5f) idx = lane * 4 + 0;
    if (v.y > 0.5f) idx = lane * 4 + 1;
    if (v.z > 0.5f) idx = lane * 4 + 2;
    if (v.w > 0.5f) idx = lane * 4 + 3;
#pragma unroll
    for (int o = 16; o; o >>= 1) idx += __shfl_xor_sync(0xffffffffu, idx, o);
    if (lane == 0) g_symbols[row] = (unsigned char)idx;
}

// Packed dual-lane fp32 ops (Blackwell f32x2) + HW tanh.
#define FMA2(d, a, b, c) \
    asm("fma.rn.f32x2 %0, %1, %2, %3;" : "=l"(d) : "l"(a), "l"(b), "l"(c))
#define ADD2(d, a, b) \
    asm("add.rn.f32x2 %0, %1, %2;" : "=l"(d) : "l"(a), "l"(b))
#define PACK2(d, lo, hi) \
    asm("mov.b64 %0, {%1, %2};" : "=l"(d) : "f"(lo), "f"(hi))
#define TANHF(d, x) \
    asm("tanh.approx.f32 %0, %1;" : "=f"(d) : "f"(x))

// Dot(W_row[tid], h) + pre, h read broadcast from shared; returns tanh(dot).
__device__ __forceinline__ float step_tanh(const float* __restrict__ hbuf,
                                           const unsigned long long* __restrict__ w2,
                                           float pre) {
    const ulonglong2* h2 = reinterpret_cast<const ulonglong2*>(hbuf);
    unsigned long long a0, a1, a2, a3;
    PACK2(a0, pre, 0.0f);
    a1 = 0; a2 = 0; a3 = 0;
#pragma unroll
    for (int c = 0; c < 16; c++) {
        ulonglong2 u = h2[2 * c];       // broadcast LDS.128
        ulonglong2 v = h2[2 * c + 1];   // broadcast LDS.128
        FMA2(a0, w2[4 * c + 0], u.x, a0);
        FMA2(a1, w2[4 * c + 1], u.y, a1);
        FMA2(a2, w2[4 * c + 2], v.x, a2);
        FMA2(a3, w2[4 * c + 3], v.y, a3);
    }
    ADD2(a0, a0, a1);
    ADD2(a2, a2, a3);
    ADD2(a0, a0, a2);
    float z = __uint_as_float((unsigned)a0)
            + __uint_as_float((unsigned)(a0 >> 32));
    float hn;
    TANHF(hn, z);
    return hn;
}

// ---------------------------------------------------------------------------
// Kernel 3: the RNN. One CTA per (scheduled) batch element, 128 threads;
// thread i owns h[i], W_hh row i in 64 packed-u64 registers.
// 2-step unrolled loop with fixed buffer roles (hb0->hb1, hb1->hb0):
// no pointer toggling, half the branch overhead. Symbol/gather pipeline runs
// 2 full steps ahead so the LDS(sym)->LDG(Wtbl) chain hides under a step.
// ---------------------------------------------------------------------------
__global__ __launch_bounds__(128, 2) void rnn_kernel(
    const float* __restrict__ W_hh,
    const float* __restrict__ b_ih,
    const float* __restrict__ b_hh,
    const float* __restrict__ W_out,
    const float* __restrict__ b_out,
    float* __restrict__ out)
{
    __shared__ __align__(16) float hb0[Hh];
    __shared__ __align__(16) float hb1[Hh];
    __shared__ __align__(16) unsigned char ssym[Tt + 16];
    __shared__ float red[2][Hh];

    const int b   = g_assign[blockIdx.x];
    const int tid = threadIdx.x;

    // Stage this row's symbols into shared (1 KB) + zero pad tail.
    {
        const uint4* src = reinterpret_cast<const uint4*>(g_symbols + (size_t)b * Tt);
        uint4* dst = reinterpret_cast<uint4*>(ssym);
        for (int i = tid; i < Tt / 16; i += 128) dst[i] = src[i];
        if (tid == 0) *reinterpret_cast<uint4*>(ssym + Tt) = make_uint4(0, 0, 0, 0);
    }

    // W_hh row tid -> 64 packed f32x2 registers.
    unsigned long long w2[64];
    {
        const ulonglong2* wr = reinterpret_cast<const ulonglong2*>(W_hh + (size_t)tid * Hh);
#pragma unroll
        for (int c = 0; c < 32; c++) {
            ulonglong2 u = wr[c];
            w2[2 * c]     = u.x;
            w2[2 * c + 1] = u.y;
        }
    }

    const float bsum = b_ih[tid] + b_hh[tid];
    hb0[tid] = 0.0f;
    __syncthreads();

    int   t  = 0;
    int   s0 = ssym[0];                              // symbol for step t   (A)
    int   s1 = ssym[1];                              // symbol for step t+1 (B)
    float pre0 = g_Wtbl[(s0 << 7) + tid] + bsum;
    float pre1 = g_Wtbl[(s1 << 7) + tid] + bsum;
    float hlast = 0.0f;
    bool  lastInHb1;                                 // which buffer holds h_last

    for (;;) {
        if (s0 <= 0) { lastInHb1 = false; break; }   // h_last committed to hb0
        // prefetch for step t+2 (consumed 2 steps later)
        int   s2   = ssym[t + 2];
        float pre2 = g_Wtbl[(s2 << 7) + tid];

        // ---- step A: hb0 -> hb1 ----
        hlast = step_tanh(hb0, w2, pre0);
        hb1[tid] = hlast;
        __syncthreads();

        if (s1 <= 0) { lastInHb1 = true; break; }    // h_last is in hb1
        // prefetch for step t+3
        int   s3   = ssym[t + 3];
        float pre3 = g_Wtbl[(s3 << 7) + tid];

        // ---- step B: hb1 -> hb0 ----
        hlast = step_tanh(hb1, w2, pre1);
        hb0[tid] = hlast;
        __syncthreads();

        t += 2;
        s0 = s2;  s1 = s3;
        pre0 = pre2 + bsum;
        pre1 = pre3 + bsum;
    }
    (void)lastInHb1;  // h_last kept in register; buffers not re-read

    // Epilogue: h_last is in hlast (register).
    float hv = hlast;
    out[2 * Bb + b * Hh + tid] = hv;               // hidden (1,B,H) at offset 512
    red[0][tid] = W_out[tid] * hv;                 // W_out row 0
    red[1][tid] = W_out[Hh + tid] * hv;            // W_out row 1
    __syncthreads();
    if (tid == 0) {
        float l0 = b_out[0], l1 = b_out[1];
#pragma unroll 8
        for (int i = 0; i < Hh; i++) { l0 += red[0][i]; l1 += red[1][i]; }
        float m  = fmaxf(l0, l1);
        float e0 = __expf(l0 - m), e1 = __expf(l1 - m);
        float inv = __fdividef(1.0f, e0 + e1);
        out[b * 2 + 0] = e0 * inv;                 // fed (B,2) at offset 0
        out[b * 2 + 1] = e1 * inv;
    }
}

// ---------------------------------------------------------------------------
extern "C" void kernel_launch(void* const* d_in, const int* in_sizes, int n_in,
                              void* d_out, int out_size) {
    (void)in_sizes; (void)n_in; (void)out_size;
    const float* x     = (const float*)d_in[0];
    const float* W_ih  = (const float*)d_in[1];
    const float* W_hh  = (const float*)d_in[2];
    const float* b_ih  = (const float*)d_in[3];
    const float* b_hh  = (const float*)d_in[4];
    const float* W_out = (const float*)d_in[5];
    const float* b_out = (const float*)d_in[6];
    float* out = (float*)d_out;

    prep_kernel<<<Bb + 128, 128>>>(x, W_ih);
    schedule_kernel<<<1, Bb>>>();
    sym_kernel<<<(Bb * Tt) / 8, 256>>>(x);
    rnn_kernel<<<Bb, 128>>>(W_hh, b_ih, b_hh, W_out, b_out, out);
}